// round 6
// baseline (speedup 1.0000x reference)
#include <cuda_runtime.h>

#define E    4096
#define NVAR 1024
#define NCHK 512
#define EPS32   1.1920929e-07f
#define LN2F    0.6931471805599453f
#define LOG2EF  1.4426950408889634f

// Upper-triangle peers of each edge (columns > row), ascending. Only rows with
// g_ucnt==7 (check representatives) have complete lists -- and those are the
// only ones decode ever reads.
__device__ int g_up[E * 7];
__device__ __align__(16) int g_ucnt[E];

// ---------------- kernel A: upper-triangle peer scan, streamed ---------------
// w_odd_to_even is symmetric, zero diagonal, 7 nonzeros per row. Warp gw
// handles rows gw and 4095-gw (combined upper-tri length = E-1: perfect
// balance). NO early exit: the loop is unconditional so ptxas batches the
// float4 loads (high MLP, DRAM-roofline streaming). Ballot compaction emits
// peers in ascending column order.
__global__ void build_peers_kernel(const float4* __restrict__ w) {
    int gw   = (blockIdx.x * blockDim.x + threadIdx.x) >> 5;   // 0..2047
    int lane = threadIdx.x & 31;
#pragma unroll
    for (int pass = 0; pass < 2; pass++) {
        int row = pass ? (E - 1 - gw) : gw;
        const float4* r = w + (size_t)row * (E / 4);
        int* dst = g_up + row * 7;
        int f0 = (row + 1) >> 2;              // first float4 with any col > row
        int iters = ((E / 4) - f0 + 31) >> 5;
        int base = 0;
#pragma unroll 4
        for (int i = 0; i < iters; i++) {
            int f = f0 + i * 32 + lane;
            float4 v = (f < E / 4) ? r[f] : make_float4(0.f, 0.f, 0.f, 0.f);
            int col = f * 4;
            int c0 = (v.x != 0.0f) & (col     > row);
            int c1 = (v.y != 0.0f) & (col + 1 > row);
            int c2 = (v.z != 0.0f) & (col + 2 > row);
            int c3 = (v.w != 0.0f) & (col + 3 > row);
            int cnt = c0 + c1 + c2 + c3;
            unsigned b0 = __ballot_sync(0xffffffffu, cnt & 1);
            unsigned b1 = __ballot_sync(0xffffffffu, cnt & 2);
            unsigned b2 = __ballot_sync(0xffffffffu, cnt & 4);
            if (b0 | b1 | b2) {               // warp-uniform, rare
                unsigned mlt = (1u << lane) - 1u;
                int prior = base + __popc(b0 & mlt) + 2 * __popc(b1 & mlt)
                                 + 4 * __popc(b2 & mlt);
                if (c0) dst[prior++] = col;
                if (c1) dst[prior++] = col + 1;
                if (c2) dst[prior++] = col + 2;
                if (c3) dst[prior++] = col + 3;
                base += __popc(b0) + 2 * __popc(b1) + 4 * __popc(b2);
            }
        }
        if (lane == 0) g_ucnt[row] = base;
    }
}

// ---------------- math helpers -----------------------------------------------
__device__ __forceinline__ float tanh_acc(float a) {
    // tanh(a) = 1 - 2/(exp(2a)+1); inf-safe (saturates to +-1)
    return 1.0f - __fdividef(2.0f, __expf(2.0f * a) + 1.0f);
}

__device__ __forceinline__ float atanh2(float v) {
    // reference clamps: v>=1 -> 1-eps, v<=-1 -> -1+eps (exact copy)
    v = (v >= 1.0f) ? (1.0f - EPS32) : v;
    v = (v <= -1.0f) ? (-1.0f + EPS32) : v;
    // 2*atanh(v) = ln((1+v)/(1-v)) = ln2*(lg2(1+v) - lg2(1-v));
    // two independent MUFU lg2 -> shorter chain than rcp-based divide
    return LN2F * (__log2f(1.0f + v) - __log2f(1.0f - v));
}

__device__ __forceinline__ float zsub(float o) {
    return (o == 0.0f) ? 1.0f : o;   // reference maps exact zeros -> identity
}

// ---------------- kernel B: full decode, one persistent block ----------------
// Thread t owns variable t (edges 4t..4t+3) in the odd stage. In the even
// stage, threads 2c and 2c+1 (same warp) cooperate on check c: each handles 4
// of its 8 edges, exchanging half-products via shfl.xor.
__global__ __launch_bounds__(1024, 1)
void decode_kernel(const float* __restrict__ x, float* __restrict__ out) {
    __shared__ float sh_odd[E];      // odd messages, natural edge order
    __shared__ float sh_even[E];     // even messages, natural edge order
    __shared__ int   chk_list[NCHK]; // representative (min) edge per check
    __shared__ int   chk_ctr;

    const int t = threadIdx.x;
    const float llr = x[t];

    if (t == 0) chk_ctr = 0;
    ((float4*)sh_even)[t] = make_float4(0.f, 0.f, 0.f, 0.f);
    __syncthreads();

    // claim checks: edge e is representative iff all 7 peers are above it
    int4 uc = ((const int4*)g_ucnt)[t];
    if (uc.x == 7) chk_list[atomicAdd(&chk_ctr, 1)] = 4 * t;
    if (uc.y == 7) chk_list[atomicAdd(&chk_ctr, 1)] = 4 * t + 1;
    if (uc.z == 7) chk_list[atomicAdd(&chk_ctr, 1)] = 4 * t + 2;
    if (uc.w == 7) chk_list[atomicAdd(&chk_ctr, 1)] = 4 * t + 3;
    __syncthreads();

    // every thread owns half a check: thread u = 2c+h handles edges
    // h==0 ? {rep, p0, p1, p2} : {p3, p4, p5, p6}   (sorted; rep = minimum)
    int e0, e1, e2, e3;
    {
        int rep = chk_list[t >> 1];
        const int* p = g_up + rep * 7;
        if (t & 1) { e0 = p[3]; e1 = p[4]; e2 = p[5]; e3 = p[6]; }
        else       { e0 = rep;  e1 = p[0]; e2 = p[1]; e3 = p[2]; }
    }

    // ---- 5 BP iterations ------------------------------------------------------
#pragma unroll 1
    for (int it = 0; it < 5; it++) {
        // odd stage: vectorized, natural order (thread t = variable t)
        float4 ev = ((float4*)sh_even)[t];
        float vs = ev.x + ev.y + ev.z + ev.w;
        float4 od;
        od.x = tanh_acc(0.5f * (llr + vs - ev.x));
        od.y = tanh_acc(0.5f * (llr + vs - ev.y));
        od.z = tanh_acc(0.5f * (llr + vs - ev.z));
        od.w = tanh_acc(0.5f * (llr + vs - ev.w));
        ((float4*)sh_odd)[t] = od;
        __syncthreads();

        // even stage: all 1024 threads, 2 per check, half-products via shfl
        float q0 = zsub(sh_odd[e0]);
        float q1 = zsub(sh_odd[e1]);
        float q2 = zsub(sh_odd[e2]);
        float q3 = zsub(sh_odd[e3]);
        float p01 = q0 * q1, p23 = q2 * q3;
        float half = p01 * p23;
        float om = __shfl_xor_sync(0xffffffffu, half, 1);  // other half's product
        sh_even[e0] = atanh2(q1 * p23 * om);
        sh_even[e1] = atanh2(q0 * p23 * om);
        sh_even[e2] = atanh2(p01 * q3 * om);
        sh_even[e3] = atanh2(p01 * q2 * om);
        __syncthreads();
    }

    // ---- epilogue: out[n] = sigmoid(x[n] + sum of even over var n) ------------
    float4 ev = ((float4*)sh_even)[t];
    float z = llr + ev.x + ev.y + ev.z + ev.w;
    out[t] = __fdividef(1.0f, 1.0f + __expf(-z));
}

// ---------------- launch ------------------------------------------------------
extern "C" void kernel_launch(void* const* d_in, const int* in_sizes, int n_in,
                              void* d_out, int out_size) {
    (void)in_sizes; (void)n_in; (void)out_size;
    const float*  x = (const float*)d_in[0];
    const float4* w = (const float4*)d_in[2];   // w_odd_to_even [E,E]
    float* out = (float*)d_out;

    build_peers_kernel<<<256, 256>>>(w);   // 2048 warps, paired rows, streamed
    decode_kernel<<<1, 1024>>>(x, out);
}